// round 1
// baseline (speedup 1.0000x reference)
#include <cuda_runtime.h>

// Problem constants (fixed shapes)
#define NN 50000
#define EE 1600000
#define DD 128

// ---------------- scratch (static device memory, allocation-free) ------------
__device__ __align__(16) float g_deg[NN];
__device__ __align__(16) float g_dinv[NN];
__device__ __align__(16) float g_w[EE];
__device__ __align__(16) float g_bufA[(long)NN * DD];
__device__ __align__(16) float g_bufB[(long)NN * DD];
__device__ __align__(16) float g_acc[(long)NN * DD];
__device__ __align__(16) float g_h[(long)NN * DD];

// ---------------- utility kernels -------------------------------------------
__global__ void k_zero(float* __restrict__ p, int n4) {
    int i = blockIdx.x * blockDim.x + threadIdx.x;
    int stride = gridDim.x * blockDim.x;
    float4 z = make_float4(0.f, 0.f, 0.f, 0.f);
    for (int j = i; j < n4; j += stride) ((float4*)p)[j] = z;
}

__global__ void k_deg(const int* __restrict__ col) {
    int e = blockIdx.x * blockDim.x + threadIdx.x;
    if (e < EE) atomicAdd(&g_deg[col[e]], 1.0f);
}

__global__ void k_dinv() {
    int i = blockIdx.x * blockDim.x + threadIdx.x;
    if (i < NN) {
        float d = g_deg[i];
        g_dinv[i] = d > 0.f ? rsqrtf(d) : 0.f;
    }
}

__global__ void k_normw(const int* __restrict__ row, const int* __restrict__ col) {
    int e = blockIdx.x * blockDim.x + threadIdx.x;
    if (e < EE) g_w[e] = g_dinv[row[e]] * g_dinv[col[e]];
}

// ---------------- propagation: nxt[col[e]] += w[e] * cur[row[e]] -------------
// One warp per edge; each lane handles one float4 (32 lanes * 4 = 128 floats).
__global__ void k_scatter(const int* __restrict__ row, const int* __restrict__ col,
                          const float* __restrict__ cur, float* __restrict__ nxt) {
    int e = blockIdx.x * (blockDim.x >> 5) + (threadIdx.x >> 5);
    if (e >= EE) return;
    int lane = threadIdx.x & 31;
    int r = 0, c = 0;
    float we = 0.f;
    if (lane == 0) { r = row[e]; c = col[e]; we = g_w[e]; }
    r = __shfl_sync(0xffffffffu, r, 0);
    c = __shfl_sync(0xffffffffu, c, 0);
    we = __shfl_sync(0xffffffffu, we, 0);

    float4 v = ((const float4*)(cur + (long)r * DD))[lane];
    v.x *= we; v.y *= we; v.z *= we; v.w *= we;
    float4* dst = ((float4*)(nxt + (long)c * DD)) + lane;
    asm volatile("red.global.add.v4.f32 [%0], {%1,%2,%3,%4};"
                 :: "l"(dst), "f"(v.x), "f"(v.y), "f"(v.z), "f"(v.w)
                 : "memory");
}

// ---------------- GEMM: C[M,128] (+)= A[M,128] @ W[128,128] ------------------
// 128x128 block tile, BK=8, 256 threads, 8x8 microtile per thread.
template <bool ACC>
__global__ void __launch_bounds__(256, 2)
k_gemm(const float* __restrict__ A, const float* __restrict__ W,
       float* __restrict__ C, int M) {
    __shared__ __align__(16) float As[8][128];
    __shared__ __align__(16) float Bs[8][128];

    int tid = threadIdx.x;
    int m0 = blockIdx.x * 128;
    int tx = tid & 15;       // 16 col groups
    int ty = tid >> 4;       // 16 row groups

    float acc[8][8];
#pragma unroll
    for (int i = 0; i < 8; i++)
#pragma unroll
        for (int j = 0; j < 8; j++) acc[i][j] = 0.f;

    // A tile load mapping: 128 rows x 8 k; each thread loads one float4.
    int a_row = tid >> 1;
    int a_col = (tid & 1) * 4;
    // B tile load mapping: 8 k-rows x 128 n; each thread loads one float4.
    int b_row = tid >> 5;
    int b_col = (tid & 31) * 4;

    for (int k0 = 0; k0 < 128; k0 += 8) {
        float4 av = make_float4(0.f, 0.f, 0.f, 0.f);
        int gr = m0 + a_row;
        if (gr < M) av = *(const float4*)(A + (long)gr * 128 + k0 + a_col);
        As[a_col + 0][a_row] = av.x;
        As[a_col + 1][a_row] = av.y;
        As[a_col + 2][a_row] = av.z;
        As[a_col + 3][a_row] = av.w;
        *(float4*)&Bs[b_row][b_col] =
            *(const float4*)(W + (long)(k0 + b_row) * 128 + b_col);
        __syncthreads();

#pragma unroll
        for (int kk = 0; kk < 8; kk++) {
            float a[8], b[8];
            *(float4*)&a[0] = *(const float4*)&As[kk][ty * 8];
            *(float4*)&a[4] = *(const float4*)&As[kk][ty * 8 + 4];
            *(float4*)&b[0] = *(const float4*)&Bs[kk][tx * 8];
            *(float4*)&b[4] = *(const float4*)&Bs[kk][tx * 8 + 4];
#pragma unroll
            for (int i = 0; i < 8; i++)
#pragma unroll
                for (int j = 0; j < 8; j++) acc[i][j] += a[i] * b[j];
        }
        __syncthreads();
    }

#pragma unroll
    for (int i = 0; i < 8; i++) {
        int gr = m0 + ty * 8 + i;
        if (gr >= M) break;
        float* cp = C + (long)gr * 128 + tx * 8;
#pragma unroll
        for (int j = 0; j < 8; j += 4) {
            float4 v = make_float4(acc[i][j], acc[i][j + 1], acc[i][j + 2], acc[i][j + 3]);
            if (ACC) {
                float4 o = *(float4*)(cp + j);
                v.x += o.x; v.y += o.y; v.z += o.z; v.w += o.w;
            }
            *(float4*)(cp + j) = v;
        }
    }
}

// ---------------- epilogue: dst = (src + b) [relu] ---------------------------
__global__ void k_bias_act(const float* __restrict__ src, const float* __restrict__ b,
                           float* __restrict__ dst, int relu) {
    long i = (long)blockIdx.x * blockDim.x + threadIdx.x;
    const long total = (long)NN * DD / 4;
    if (i >= total) return;
    float4 v = ((const float4*)src)[i];
    float4 bb = ((const float4*)b)[i & (DD / 4 - 1)];
    v.x += bb.x; v.y += bb.y; v.z += bb.z; v.w += bb.w;
    if (relu) {
        v.x = fmaxf(v.x, 0.f); v.y = fmaxf(v.y, 0.f);
        v.z = fmaxf(v.z, 0.f); v.w = fmaxf(v.w, 0.f);
    }
    ((float4*)dst)[i] = v;
}

// ---------------- host orchestration -----------------------------------------
extern "C" void kernel_launch(void* const* d_in, const int* in_sizes, int n_in,
                              void* d_out, int out_size) {
    const float* x  = (const float*)d_in[0];
    const int*   ei = (const int*)d_in[1];
    const float* W1 = (const float*)d_in[2];
    const float* b1 = (const float*)d_in[3];
    const float* W2 = (const float*)d_in[4];
    const float* b2 = (const float*)d_in[5];
    const float* W3 = (const float*)d_in[6];
    const float* b3 = (const float*)d_in[7];
    const float* Wf = (const float*)d_in[8];
    const float* bf = (const float*)d_in[9];
    float* out = (float*)d_out;

    const int* row = ei;
    const int* col = ei + EE;

    float *p_deg, *p_bufA, *p_bufB, *p_acc, *p_h;
    cudaGetSymbolAddress((void**)&p_deg,  g_deg);
    cudaGetSymbolAddress((void**)&p_bufA, g_bufA);
    cudaGetSymbolAddress((void**)&p_bufB, g_bufB);
    cudaGetSymbolAddress((void**)&p_acc,  g_acc);
    cudaGetSymbolAddress((void**)&p_h,    g_h);

    const int ND4 = NN * DD / 4;        // 1.6M float4
    const int gemm_grid = (NN + 127) / 128;  // 391
    const int scat_grid = EE / 8;       // 8 warps (edges) per 256-thread block

    // --- normalization ---
    k_zero<<<128, 256>>>(p_deg, NN / 4);
    k_deg<<<(EE + 255) / 256, 256>>>(col);
    k_dinv<<<(NN + 255) / 256, 256>>>();
    k_normw<<<(EE + 255) / 256, 256>>>(row, col);

    const float* Ws[3] = {W1, W2, W3};
    const float* bs[3] = {b1, b2, b3};
    const float* F = x;

    for (int l = 0; l < 3; l++) {
        // out = F @ W[0]
        k_gemm<false><<<gemm_grid, 256>>>(F, Ws[l], p_acc, NN);

        const float* cur = F;
        float* dst = p_bufA;
        for (int k = 1; k <= 3; k++) {
            k_zero<<<2048, 256>>>(dst, ND4);
            k_scatter<<<scat_grid, 256>>>(row, col, cur, dst);
            k_gemm<true><<<gemm_grid, 256>>>(dst, Ws[l] + (long)k * DD * DD, p_acc, NN);
            cur = dst;
            dst = (dst == p_bufA) ? p_bufB : p_bufA;
        }
        // h = relu(out + b)
        k_bias_act<<<(ND4 + 255) / 256, 256>>>(p_acc, bs[l], p_h, 1);
        F = p_h;
    }

    // z = h @ Wf + bf
    k_gemm<false><<<gemm_grid, 256>>>(p_h, Wf, p_acc, NN);
    k_bias_act<<<(ND4 + 255) / 256, 256>>>(p_acc, bf, out, 0);
}

// round 2
// speedup vs baseline: 2.0046x; 2.0046x over previous
#include <cuda_runtime.h>

#define NN 50000
#define EE 1600000
#define DD 128

// ---------------- scratch (static device memory, allocation-free) ------------
__device__ __align__(16) int    g_degi[NN];
__device__ __align__(16) int    g_fill[NN];
__device__ __align__(16) int    g_rowptr[NN + 1];
__device__ __align__(16) float  g_dinv[NN];
__device__ __align__(16) float2 g_csr[EE];          // .x = src (bits), .y = weight
__device__ __align__(16) float  g_p1[(long)NN * DD];
__device__ __align__(16) float  g_p2[(long)NN * DD];
__device__ __align__(16) float  g_p3[(long)NN * DD];
__device__ __align__(16) float  g_h1[(long)NN * DD];
__device__ __align__(16) float  g_h2[(long)NN * DD];

// ---------------- normalization + CSR build ----------------------------------
__global__ void k_zero_i(int* __restrict__ p, int n) {
    int i = blockIdx.x * blockDim.x + threadIdx.x;
    if (i < n) p[i] = 0;
}

__global__ void k_deg(const int* __restrict__ col) {
    int e = blockIdx.x * blockDim.x + threadIdx.x;
    if (e < EE) atomicAdd(&g_degi[col[e]], 1);
}

__global__ void k_dinv() {
    int i = blockIdx.x * blockDim.x + threadIdx.x;
    if (i < NN) {
        int d = g_degi[i];
        g_dinv[i] = d > 0 ? rsqrtf((float)d) : 0.f;
    }
}

// Single-block exclusive prefix scan of g_degi -> g_rowptr (N=50000).
__global__ void k_scan() {
    __shared__ int warp_excl[32];
    __shared__ int carry_sh;
    int tid = threadIdx.x, lane = tid & 31, wid = tid >> 5;
    if (tid == 0) carry_sh = 0;
    __syncthreads();
    for (int base = 0; base < NN; base += 1024) {
        int idx = base + tid;
        int v = (idx < NN) ? g_degi[idx] : 0;
        int incl = v;
#pragma unroll
        for (int o = 1; o < 32; o <<= 1) {
            int t = __shfl_up_sync(0xffffffffu, incl, o);
            if (lane >= o) incl += t;
        }
        if (lane == 31) warp_excl[wid] = incl;
        __syncthreads();
        if (wid == 0) {
            int t = warp_excl[lane];
            int ti = t;
#pragma unroll
            for (int o = 1; o < 32; o <<= 1) {
                int u = __shfl_up_sync(0xffffffffu, ti, o);
                if (lane >= o) ti += u;
            }
            warp_excl[lane] = ti - t;  // exclusive of warp totals
        }
        __syncthreads();
        int excl = carry_sh + warp_excl[wid] + incl - v;
        if (idx < NN) g_rowptr[idx] = excl;
        __syncthreads();
        if (tid == 1023) carry_sh = excl + v;
        __syncthreads();
    }
    if (threadIdx.x == 0) g_rowptr[NN] = carry_sh;
}

__global__ void k_fill(const int* __restrict__ row, const int* __restrict__ col) {
    int e = blockIdx.x * blockDim.x + threadIdx.x;
    if (e >= EE) return;
    int s = row[e], c = col[e];
    int p = atomicAdd(&g_fill[c], 1) + g_rowptr[c];
    float2 ent;
    ent.x = __int_as_float(s);
    ent.y = g_dinv[s] * g_dinv[c];
    g_csr[p] = ent;
}

// ---------------- SpMM gather: out[i] = sum_{e: dst=i} w_e * cur[src_e] ------
// One warp per node; lane owns one float4 (32*4 = 128 floats).
__global__ void __launch_bounds__(256)
k_spmm(const float* __restrict__ cur, float* __restrict__ outp) {
    int node = blockIdx.x * 8 + (threadIdx.x >> 5);
    if (node >= NN) return;
    int lane = threadIdx.x & 31;
    int s = __ldg(&g_rowptr[node]);
    int e = __ldg(&g_rowptr[node + 1]);

    float4 acc = make_float4(0.f, 0.f, 0.f, 0.f);
    int i = s;
    for (; i + 1 < e; i += 2) {
        float2 c0 = __ldg(&g_csr[i]);
        float2 c1 = __ldg(&g_csr[i + 1]);
        int s0 = __float_as_int(c0.x);
        int s1 = __float_as_int(c1.x);
        float4 v0 = __ldg(((const float4*)(cur + (long)s0 * DD)) + lane);
        float4 v1 = __ldg(((const float4*)(cur + (long)s1 * DD)) + lane);
        acc.x += c0.y * v0.x + c1.y * v1.x;
        acc.y += c0.y * v0.y + c1.y * v1.y;
        acc.z += c0.y * v0.z + c1.y * v1.z;
        acc.w += c0.y * v0.w + c1.y * v1.w;
    }
    if (i < e) {
        float2 c0 = __ldg(&g_csr[i]);
        int s0 = __float_as_int(c0.x);
        float4 v0 = __ldg(((const float4*)(cur + (long)s0 * DD)) + lane);
        acc.x += c0.y * v0.x;
        acc.y += c0.y * v0.y;
        acc.z += c0.y * v0.z;
        acc.w += c0.y * v0.w;
    }
    ((float4*)(outp + (long)node * DD))[lane] = acc;
}

// ---------------- GEMM: C[M,128] = relu?( cat(A0..A{NMAT-1}) @ W + b ) -------
// 128x128 tile, BK=8, 256 threads, 8x8 microtile. K = NMAT*128.
struct APtrs { const float* p[4]; };

template <int NMAT, bool RELU>
__global__ void __launch_bounds__(256, 2)
k_gemm(APtrs A, const float* __restrict__ W, const float* __restrict__ bias,
       float* __restrict__ C, int M) {
    __shared__ __align__(16) float As[8][128];
    __shared__ __align__(16) float Bs[8][128];

    int tid = threadIdx.x;
    int m0 = blockIdx.x * 128;
    int tx = tid & 15;
    int ty = tid >> 4;

    float acc[8][8];
#pragma unroll
    for (int i = 0; i < 8; i++)
#pragma unroll
        for (int j = 0; j < 8; j++) acc[i][j] = 0.f;

    int a_row = tid >> 1;
    int a_col = (tid & 1) * 4;
    int b_row = tid >> 5;
    int b_col = (tid & 31) * 4;
    int gr = m0 + a_row;

    for (int k0 = 0; k0 < NMAT * 128; k0 += 8) {
        const float* Ap = A.p[k0 >> 7];
        int koff = k0 & 127;
        float4 av = make_float4(0.f, 0.f, 0.f, 0.f);
        if (gr < M) av = *(const float4*)(Ap + (long)gr * 128 + koff + a_col);
        As[a_col + 0][a_row] = av.x;
        As[a_col + 1][a_row] = av.y;
        As[a_col + 2][a_row] = av.z;
        As[a_col + 3][a_row] = av.w;
        *(float4*)&Bs[b_row][b_col] =
            *(const float4*)(W + (long)(k0 + b_row) * 128 + b_col);
        __syncthreads();

#pragma unroll
        for (int kk = 0; kk < 8; kk++) {
            float a[8], b[8];
            *(float4*)&a[0] = *(const float4*)&As[kk][ty * 8];
            *(float4*)&a[4] = *(const float4*)&As[kk][ty * 8 + 4];
            *(float4*)&b[0] = *(const float4*)&Bs[kk][tx * 8];
            *(float4*)&b[4] = *(const float4*)&Bs[kk][tx * 8 + 4];
#pragma unroll
            for (int i = 0; i < 8; i++)
#pragma unroll
                for (int j = 0; j < 8; j++) acc[i][j] += a[i] * b[j];
        }
        __syncthreads();
    }

    float bb[8];
#pragma unroll
    for (int j = 0; j < 8; j++) bb[j] = __ldg(&bias[tx * 8 + j]);

#pragma unroll
    for (int i = 0; i < 8; i++) {
        int r = m0 + ty * 8 + i;
        if (r >= M) break;
        float* cp = C + (long)r * 128 + tx * 8;
#pragma unroll
        for (int j = 0; j < 8; j += 4) {
            float4 v;
            v.x = acc[i][j + 0] + bb[j + 0];
            v.y = acc[i][j + 1] + bb[j + 1];
            v.z = acc[i][j + 2] + bb[j + 2];
            v.w = acc[i][j + 3] + bb[j + 3];
            if (RELU) {
                v.x = fmaxf(v.x, 0.f); v.y = fmaxf(v.y, 0.f);
                v.z = fmaxf(v.z, 0.f); v.w = fmaxf(v.w, 0.f);
            }
            *(float4*)(cp + j) = v;
        }
    }
}

// ---------------- host orchestration -----------------------------------------
extern "C" void kernel_launch(void* const* d_in, const int* in_sizes, int n_in,
                              void* d_out, int out_size) {
    const float* x  = (const float*)d_in[0];
    const int*   ei = (const int*)d_in[1];
    const float* W1 = (const float*)d_in[2];
    const float* b1 = (const float*)d_in[3];
    const float* W2 = (const float*)d_in[4];
    const float* b2 = (const float*)d_in[5];
    const float* W3 = (const float*)d_in[6];
    const float* b3 = (const float*)d_in[7];
    const float* Wf = (const float*)d_in[8];
    const float* bf = (const float*)d_in[9];
    float* out = (float*)d_out;

    const int* row = ei;
    const int* col = ei + EE;

    int *p_degi, *p_fill;
    float *p_p1, *p_p2, *p_p3, *p_h1, *p_h2;
    cudaGetSymbolAddress((void**)&p_degi, g_degi);
    cudaGetSymbolAddress((void**)&p_fill, g_fill);
    cudaGetSymbolAddress((void**)&p_p1, g_p1);
    cudaGetSymbolAddress((void**)&p_p2, g_p2);
    cudaGetSymbolAddress((void**)&p_p3, g_p3);
    cudaGetSymbolAddress((void**)&p_h1, g_h1);
    cudaGetSymbolAddress((void**)&p_h2, g_h2);

    const int gemm_grid = (NN + 127) / 128;  // 391
    const int spmm_grid = (NN + 7) / 8;      // 6250
    const int egrid = (EE + 255) / 256;
    const int ngrid = (NN + 255) / 256;

    // --- normalization + CSR build ---
    k_zero_i<<<ngrid, 256>>>(p_degi, NN);
    k_zero_i<<<ngrid, 256>>>(p_fill, NN);
    k_deg<<<egrid, 256>>>(col);
    k_dinv<<<ngrid, 256>>>();
    k_scan<<<1, 1024>>>();
    k_fill<<<egrid, 256>>>(row, col);

    const float* Ws[3] = {W1, W2, W3};
    const float* bs[3] = {b1, b2, b3};

    const float* F = x;
    float* Hs[3] = {p_h1, p_h2, p_h1};

    for (int l = 0; l < 3; l++) {
        k_spmm<<<spmm_grid, 256>>>(F, p_p1);
        k_spmm<<<spmm_grid, 256>>>(p_p1, p_p2);
        k_spmm<<<spmm_grid, 256>>>(p_p2, p_p3);
        APtrs A;
        A.p[0] = F; A.p[1] = p_p1; A.p[2] = p_p2; A.p[3] = p_p3;
        k_gemm<4, true><<<gemm_grid, 256>>>(A, Ws[l], bs[l], Hs[l], NN);
        F = Hs[l];
    }

    APtrs Af;
    Af.p[0] = F; Af.p[1] = F; Af.p[2] = F; Af.p[3] = F;
    k_gemm<1, false><<<gemm_grid, 256>>>(Af, Wf, bf, out, NN);
}